// round 7
// baseline (speedup 1.0000x reference)
#include <cuda_runtime.h>
#include <cuda_bf16.h>

// Problem constants: x[16,512,32,32], Q/K/V[512,512]
#define B_ 16
#define C_ 512
#define S_ 1024
#define BS_ (B_ * S_)   // 16384

// -------- scratch (device globals; no allocation allowed) --------
__device__ float g_xn[B_ * S_ * C_];     // normalized x, [B,S,C]
__device__ float g_q [B_ * S_ * C_];
__device__ float g_k [B_ * S_ * C_];
__device__ float g_v [B_ * S_ * C_];
__device__ float g_sc[B_ * S_ * S_];     // scores / attn weights, [B,S,S]
__device__ float g_mean[C_];
__device__ float g_rsig[C_];

// -------- packed f32x2 helpers (sm_100+ PTX) --------
__device__ __forceinline__ unsigned long long ffma2(unsigned long long a,
                                                    unsigned long long b,
                                                    unsigned long long c) {
    unsigned long long d;
    asm("fma.rn.f32x2 %0, %1, %2, %3;" : "=l"(d) : "l"(a), "l"(b), "l"(c));
    return d;
}
__device__ __forceinline__ float2 unpack2(unsigned long long v) {
    float2 r;
    asm("mov.b64 {%0, %1}, %2;" : "=f"(r.x), "=f"(r.y) : "l"(v));
    return r;
}

// -------- BatchNorm statistics: one block per channel --------
__global__ __launch_bounds__(256) void bn_stats_kernel(const float* __restrict__ x) {
    int c = blockIdx.x;
    int t = threadIdx.x;
    float s = 0.f, ss = 0.f;
    for (int b = 0; b < B_; ++b) {
        const float* p = x + ((size_t)b * C_ + c) * S_;
        for (int i = t; i < S_; i += 256) {
            float v = p[i];
            s += v;
            ss += v * v;
        }
    }
    #pragma unroll
    for (int o = 16; o > 0; o >>= 1) {
        s  += __shfl_down_sync(0xffffffffu, s,  o);
        ss += __shfl_down_sync(0xffffffffu, ss, o);
    }
    __shared__ float shs[8], shq[8];
    int w = t >> 5, l = t & 31;
    if (l == 0) { shs[w] = s; shq[w] = ss; }
    __syncthreads();
    if (t == 0) {
        float S = 0.f, Qq = 0.f;
        #pragma unroll
        for (int i = 0; i < 8; ++i) { S += shs[i]; Qq += shq[i]; }
        const float invN = 1.0f / (float)(B_ * S_);
        float mu  = S * invN;
        float var = Qq * invN - mu * mu;
        g_mean[c] = mu;
        g_rsig[c] = rsqrtf(var + 1e-5f);
    }
}

// -------- normalize + transpose [B,C,S] -> [B,S,C] --------
__global__ __launch_bounds__(256) void normalize_kernel(const float* __restrict__ x) {
    __shared__ float tile[32][33];
    int b  = blockIdx.z;
    int c0 = blockIdx.y * 32;
    int s0 = blockIdx.x * 32;
    int tx = threadIdx.x, ty = threadIdx.y;   // blockDim (32, 8)
    #pragma unroll
    for (int r = 0; r < 4; ++r) {
        int c = c0 + ty + 8 * r;
        tile[ty + 8 * r][tx] = x[((size_t)b * C_ + c) * S_ + s0 + tx];
    }
    __syncthreads();
    float mu = g_mean[c0 + tx];
    float rs = g_rsig[c0 + tx];
    #pragma unroll
    for (int r = 0; r < 4; ++r) {
        int s = s0 + ty + 8 * r;
        g_xn[((size_t)b * S_ + s) * C_ + c0 + tx] = (tile[tx][ty + 8 * r] - mu) * rs;
    }
}

// -------- fp32 GEMM (f32x2 packed FMA), 128x128x16 tile, 8x8/thread --------
// A stored in smem as DUPLICATED pairs (each value twice) so the inner loop
// loads ready-made f32x2 operands: no per-kk pack MOVs.
// Double-buffered smem, LDG prefetch into registers, ONE sync per k-iter.
// C[z] = alpha * A[z] * op(B[z])  (+ Res[z] if ADD_RES), op = transpose if TRANSB.
template <bool TRANSB, bool ADD_RES>
__global__ __launch_bounds__(256, 2) void gemm_kernel(
    const float* __restrict__ Ag, const float* __restrict__ Bg,
    float* __restrict__ Cg, const float* __restrict__ Res,
    int M, int N, int K,
    size_t sA, size_t sB, size_t sC, float alpha)
{
    __shared__ float As[2][16][256];   // dup-pairs: As[k][2m],As[k][2m+1] = A[m][k]
    __shared__ float Bs[2][16][128];   // natural:   Bs[k][n]

    const int tid = threadIdx.x;
    const int tx  = tid & 15;          // n-tile coord
    const int ty  = tid >> 4;          // m-tile coord
    const int lr  = tid >> 2;          // transpose-load row (0..63)
    const int lc  = (tid & 3) * 4;     // transpose-load k offset
    const int bk  = tid >> 5;          // NN B-load k row (0..7)
    const int bn  = (tid & 31) * 4;    // NN B-load n offset

    const float* A = Ag + blockIdx.z * sA + (size_t)blockIdx.y * 128 * K;
    const float* Bp;
    if (TRANSB) Bp = Bg + blockIdx.z * sB + (size_t)blockIdx.x * 128 * K;
    else        Bp = Bg + blockIdx.z * sB + (size_t)blockIdx.x * 128;
    float*       Cp = Cg + blockIdx.z * sC + (size_t)blockIdx.y * 128 * N + (size_t)blockIdx.x * 128;
    const float* Rp = ADD_RES
        ? (Res + blockIdx.z * sC + (size_t)blockIdx.y * 128 * N + (size_t)blockIdx.x * 128)
        : nullptr;

    unsigned long long acc[8][4];
    #pragma unroll
    for (int i = 0; i < 8; ++i)
        #pragma unroll
        for (int j = 0; j < 4; ++j) acc[i][j] = 0ull;

    float4 a0, a1, b0, b1;   // in-flight tile (registers)

    auto LOAD = [&](int k0) {
        a0 = *(const float4*)(A + (size_t)lr * K + k0 + lc);
        a1 = *(const float4*)(A + (size_t)(lr + 64) * K + k0 + lc);
        if (TRANSB) {
            b0 = *(const float4*)(Bp + (size_t)lr * K + k0 + lc);
            b1 = *(const float4*)(Bp + (size_t)(lr + 64) * K + k0 + lc);
        } else {
            b0 = *(const float4*)(Bp + (size_t)(k0 + bk) * N + bn);
            b1 = *(const float4*)(Bp + (size_t)(k0 + bk + 8) * N + bn);
        }
    };
    auto STORE = [&](int buf) {
        // A transpose + duplicate: STS.64 per element (same count as scalar STS)
        *(float2*)&As[buf][lc + 0][2 * lr]       = make_float2(a0.x, a0.x);
        *(float2*)&As[buf][lc + 1][2 * lr]       = make_float2(a0.y, a0.y);
        *(float2*)&As[buf][lc + 2][2 * lr]       = make_float2(a0.z, a0.z);
        *(float2*)&As[buf][lc + 3][2 * lr]       = make_float2(a0.w, a0.w);
        *(float2*)&As[buf][lc + 0][2 * lr + 128] = make_float2(a1.x, a1.x);
        *(float2*)&As[buf][lc + 1][2 * lr + 128] = make_float2(a1.y, a1.y);
        *(float2*)&As[buf][lc + 2][2 * lr + 128] = make_float2(a1.z, a1.z);
        *(float2*)&As[buf][lc + 3][2 * lr + 128] = make_float2(a1.w, a1.w);
        if (TRANSB) {
            Bs[buf][lc + 0][lr]      = b0.x; Bs[buf][lc + 1][lr]      = b0.y;
            Bs[buf][lc + 2][lr]      = b0.z; Bs[buf][lc + 3][lr]      = b0.w;
            Bs[buf][lc + 0][lr + 64] = b1.x; Bs[buf][lc + 1][lr + 64] = b1.y;
            Bs[buf][lc + 2][lr + 64] = b1.z; Bs[buf][lc + 3][lr + 64] = b1.w;
        } else {
            *(float4*)&Bs[buf][bk][bn]     = b0;
            *(float4*)&Bs[buf][bk + 8][bn] = b1;
        }
    };
    auto COMPUTE = [&](int buf) {
        #pragma unroll
        for (int kk = 0; kk < 16; ++kk) {
            // A: 4x LDS.128 of duplicated pairs -> 8 ready f32x2 operands
            ulonglong2 u0 = *(const ulonglong2*)&As[buf][kk][8 * ty];
            ulonglong2 u1 = *(const ulonglong2*)&As[buf][kk][8 * ty + 4];
            ulonglong2 u2 = *(const ulonglong2*)&As[buf][kk][128 + 8 * ty];
            ulonglong2 u3 = *(const ulonglong2*)&As[buf][kk][128 + 8 * ty + 4];
            unsigned long long ap[8] = { u0.x, u0.y, u1.x, u1.y,
                                         u2.x, u2.y, u3.x, u3.y };
            ulonglong2 bb0 = *(const ulonglong2*)&Bs[buf][kk][tx * 4];
            ulonglong2 bb1 = *(const ulonglong2*)&Bs[buf][kk][64 + tx * 4];
            unsigned long long bB[4] = { bb0.x, bb0.y, bb1.x, bb1.y };
            #pragma unroll
            for (int i = 0; i < 8; ++i) {
                #pragma unroll
                for (int j = 0; j < 4; ++j)
                    acc[i][j] = ffma2(ap[i], bB[j], acc[i][j]);
            }
        }
    };

    // ---- pipelined mainloop: one __syncthreads per k-iteration ----
    LOAD(0);
    STORE(0);
    __syncthreads();
    int buf = 0;
    for (int k0 = 16; k0 < K; k0 += 16) {
        LOAD(k0);          // prefetch next tile (latency hidden by COMPUTE)
        COMPUTE(buf);
        STORE(buf ^ 1);
        __syncthreads();
        buf ^= 1;
    }
    COMPUTE(buf);

    // ---- epilogue ----
    #pragma unroll
    for (int i = 0; i < 8; ++i) {
        int row = (i < 4) ? (ty * 4 + i) : (64 + ty * 4 + (i - 4));
        float2 p0 = unpack2(acc[i][0]);
        float2 p1 = unpack2(acc[i][1]);
        float2 p2 = unpack2(acc[i][2]);
        float2 p3 = unpack2(acc[i][3]);
        float4 lo = make_float4(p0.x * alpha, p0.y * alpha, p1.x * alpha, p1.y * alpha);
        float4 hi = make_float4(p2.x * alpha, p2.y * alpha, p3.x * alpha, p3.y * alpha);
        size_t base = (size_t)row * N;
        if (ADD_RES) {
            float4 r0 = *(const float4*)(Rp + base + tx * 4);
            float4 r1 = *(const float4*)(Rp + base + 64 + tx * 4);
            lo.x += r0.x; lo.y += r0.y; lo.z += r0.z; lo.w += r0.w;
            hi.x += r1.x; hi.y += r1.y; hi.z += r1.z; hi.w += r1.w;
        }
        *(float4*)(Cp + base + tx * 4)      = lo;
        *(float4*)(Cp + base + 64 + tx * 4) = hi;
    }
}

// -------- softmax over the BATCH axis: one thread per (q,k) pair --------
__global__ __launch_bounds__(256) void softmax_batch_kernel() {
    int idx = blockIdx.x * 256 + threadIdx.x;     // < S_*S_
    float v[B_];
    float m = -3.4e38f;
    #pragma unroll
    for (int b = 0; b < B_; ++b) {
        v[b] = g_sc[(size_t)b * (S_ * S_) + idx];
        m = fmaxf(m, v[b]);
    }
    float s = 0.f;
    #pragma unroll
    for (int b = 0; b < B_; ++b) {
        v[b] = expf(v[b] - m);
        s += v[b];
    }
    float inv = 1.0f / s;
    #pragma unroll
    for (int b = 0; b < B_; ++b)
        g_sc[(size_t)b * (S_ * S_) + idx] = v[b] * inv;
}

extern "C" void kernel_launch(void* const* d_in, const int* in_sizes, int n_in,
                              void* d_out, int out_size) {
    const float* x = (const float*)d_in[0];
    const float* Q = (const float*)d_in[1];
    const float* K = (const float*)d_in[2];
    const float* V = (const float*)d_in[3];
    float* out = (float*)d_out;

    float *xn, *q, *k, *v, *sc;
    cudaGetSymbolAddress((void**)&xn, g_xn);
    cudaGetSymbolAddress((void**)&q,  g_q);
    cudaGetSymbolAddress((void**)&k,  g_k);
    cudaGetSymbolAddress((void**)&v,  g_v);
    cudaGetSymbolAddress((void**)&sc, g_sc);

    // 1) BatchNorm stats (per channel over B*S)
    bn_stats_kernel<<<C_, 256>>>(x);

    // 2) normalize + transpose -> xn [B,S,C]
    normalize_kernel<<<dim3(S_ / 32, C_ / 32, B_), dim3(32, 8)>>>(x);

    // 3) q/k/v = xn @ {Q,K,V}   [16384,512] x [512,512]
    dim3 g1(C_ / 128, BS_ / 128, 1);
    gemm_kernel<false, false><<<g1, 256>>>(xn, Q, q, nullptr, BS_, C_, C_, 0, 0, 0, 1.0f);
    gemm_kernel<false, false><<<g1, 256>>>(xn, K, k, nullptr, BS_, C_, C_, 0, 0, 0, 1.0f);
    gemm_kernel<false, false><<<g1, 256>>>(xn, V, v, nullptr, BS_, C_, C_, 0, 0, 0, 1.0f);

    // 4) scores[b] = (q[b] @ k[b]^T) / sqrt(C)   (NT, batched)
    dim3 g2(S_ / 128, S_ / 128, B_);
    gemm_kernel<true, false><<<g2, 256>>>(q, k, sc, nullptr, S_, S_, C_,
                                          (size_t)S_ * C_, (size_t)S_ * C_,
                                          (size_t)S_ * S_, 0.04419417382415922f);

    // 5) softmax over batch axis (Softmax2d quirk)
    softmax_batch_kernel<<<(S_ * S_) / 256, 256>>>();

    // 6) out[b] = attn_w[b] @ v[b] + xn[b]   (NN, batched, fused residual)
    dim3 g3(C_ / 128, S_ / 128, B_);
    gemm_kernel<false, true><<<g3, 256>>>(sc, v, out, xn, S_, C_, S_,
                                          (size_t)S_ * S_, (size_t)S_ * C_,
                                          (size_t)S_ * C_, 1.0f);
}

// round 8
// speedup vs baseline: 1.1559x; 1.1559x over previous
#include <cuda_runtime.h>
#include <cuda_bf16.h>

// Problem constants: x[16,512,32,32], Q/K/V[512,512]
#define B_ 16
#define C_ 512
#define S_ 1024
#define BS_ (B_ * S_)   // 16384

// -------- scratch (device globals; no allocation allowed) --------
__device__ float g_xn[B_ * S_ * C_];     // normalized x, [B,S,C]
__device__ float g_q [B_ * S_ * C_];
__device__ float g_k [B_ * S_ * C_];
__device__ float g_v [B_ * S_ * C_];
__device__ float g_sc[B_ * S_ * S_];     // scores / attn weights, [B,S,S]
__device__ float g_mean[C_];
__device__ float g_rsig[C_];

// -------- packed f32x2 helpers (sm_100+ PTX) --------
__device__ __forceinline__ unsigned long long ffma2(unsigned long long a,
                                                    unsigned long long b,
                                                    unsigned long long c) {
    unsigned long long d;
    asm("fma.rn.f32x2 %0, %1, %2, %3;" : "=l"(d) : "l"(a), "l"(b), "l"(c));
    return d;
}
__device__ __forceinline__ unsigned long long pack2(float x) {
    unsigned long long d;
    asm("mov.b64 %0, {%1, %1};" : "=l"(d) : "f"(x));
    return d;
}
__device__ __forceinline__ float2 unpack2(unsigned long long v) {
    float2 r;
    asm("mov.b64 {%0, %1}, %2;" : "=f"(r.x), "=f"(r.y) : "l"(v));
    return r;
}

// -------- BatchNorm statistics: one block per channel --------
__global__ __launch_bounds__(256) void bn_stats_kernel(const float* __restrict__ x) {
    int c = blockIdx.x;
    int t = threadIdx.x;
    float s = 0.f, ss = 0.f;
    for (int b = 0; b < B_; ++b) {
        const float* p = x + ((size_t)b * C_ + c) * S_;
        for (int i = t; i < S_; i += 256) {
            float v = p[i];
            s += v;
            ss += v * v;
        }
    }
    #pragma unroll
    for (int o = 16; o > 0; o >>= 1) {
        s  += __shfl_down_sync(0xffffffffu, s,  o);
        ss += __shfl_down_sync(0xffffffffu, ss, o);
    }
    __shared__ float shs[8], shq[8];
    int w = t >> 5, l = t & 31;
    if (l == 0) { shs[w] = s; shq[w] = ss; }
    __syncthreads();
    if (t == 0) {
        float S = 0.f, Qq = 0.f;
        #pragma unroll
        for (int i = 0; i < 8; ++i) { S += shs[i]; Qq += shq[i]; }
        const float invN = 1.0f / (float)(B_ * S_);
        float mu  = S * invN;
        float var = Qq * invN - mu * mu;
        g_mean[c] = mu;
        g_rsig[c] = rsqrtf(var + 1e-5f);
    }
}

// -------- normalize + transpose [B,C,S] -> [B,S,C] --------
__global__ __launch_bounds__(256) void normalize_kernel(const float* __restrict__ x) {
    __shared__ float tile[32][33];
    int b  = blockIdx.z;
    int c0 = blockIdx.y * 32;
    int s0 = blockIdx.x * 32;
    int tx = threadIdx.x, ty = threadIdx.y;   // blockDim (32, 8)
    #pragma unroll
    for (int r = 0; r < 4; ++r) {
        int c = c0 + ty + 8 * r;
        tile[ty + 8 * r][tx] = x[((size_t)b * C_ + c) * S_ + s0 + tx];
    }
    __syncthreads();
    float mu = g_mean[c0 + tx];
    float rs = g_rsig[c0 + tx];
    #pragma unroll
    for (int r = 0; r < 4; ++r) {
        int s = s0 + ty + 8 * r;
        g_xn[((size_t)b * S_ + s) * C_ + c0 + tx] = (tile[tx][ty + 8 * r] - mu) * rs;
    }
}

// -------- fp32 GEMM, 128x256x16 tile, 8x16/thread, f32x2 FMA -------------
// Reduces smem bytes/FMA to 1.5 (vs 2.0 at 8x8): LDS no longer co-limits fma.
// Double-buffered smem, LDG prefetch into registers, ONE sync per k-iter.
// C[z] = alpha * A[z] * op(B[z])  (+ Res[z] if ADD_RES), op = transpose if TRANSB.
// M % 128 == 0, N % 256 == 0, K % 16 == 0.
template <bool TRANSB, bool ADD_RES>
__global__ __launch_bounds__(256, 1) void gemm_kernel(
    const float* __restrict__ Ag, const float* __restrict__ Bg,
    float* __restrict__ Cg, const float* __restrict__ Res,
    int M, int N, int K,
    size_t sA, size_t sB, size_t sC, float alpha)
{
    __shared__ float As[2][16][128];   // As[k][m]
    __shared__ float Bs[2][16][256];   // Bs[k][n]   (total = exactly 48 KB)

    const int tid = threadIdx.x;
    const int tx  = tid & 15;          // n-group (4 chunks of 4 at stride 64)
    const int ty  = tid >> 4;          // m-group (2 chunks of 4 at stride 64)
    // A loader: each thread owns one m-row, half the k-width
    const int arow = tid >> 1;             // 0..127
    const int ak   = (tid & 1) * 8;        // 0 or 8
    // B loader (NN): 4 rows x 64 float4-chunks
    const int bro  = tid >> 6;             // 0..3
    const int bco  = (tid & 63) * 4;       // 0..252

    const float* A = Ag + blockIdx.z * sA + (size_t)blockIdx.y * 128 * K;
    const float* Bp;
    if (TRANSB) Bp = Bg + blockIdx.z * sB + (size_t)blockIdx.x * 256 * K;
    else        Bp = Bg + blockIdx.z * sB + (size_t)blockIdx.x * 256;
    float*       Cp = Cg + blockIdx.z * sC + (size_t)blockIdx.y * 128 * N + (size_t)blockIdx.x * 256;
    const float* Rp = ADD_RES
        ? (Res + blockIdx.z * sC + (size_t)blockIdx.y * 128 * N + (size_t)blockIdx.x * 256)
        : nullptr;

    unsigned long long acc[8][8];      // [m-frag][n-pair]  = 128 regs
    #pragma unroll
    for (int i = 0; i < 8; ++i)
        #pragma unroll
        for (int j = 0; j < 8; ++j) acc[i][j] = 0ull;

    float4 a0, a1;          // A prefetch: 8 k-values of row arow
    float4 bv0, bv1, bv2, bv3;  // B prefetch

    auto LOAD = [&](int k0) {
        a0 = *(const float4*)(A + (size_t)arow * K + k0 + ak);
        a1 = *(const float4*)(A + (size_t)arow * K + k0 + ak + 4);
        if (TRANSB) {
            // B[n][k] row-major: one n-row (tid) x 16 k
            const float* br = Bp + (size_t)tid * K + k0;
            bv0 = *(const float4*)(br + 0);
            bv1 = *(const float4*)(br + 4);
            bv2 = *(const float4*)(br + 8);
            bv3 = *(const float4*)(br + 12);
        } else {
            bv0 = *(const float4*)(Bp + (size_t)(k0 + bro + 0)  * N + bco);
            bv1 = *(const float4*)(Bp + (size_t)(k0 + bro + 4)  * N + bco);
            bv2 = *(const float4*)(Bp + (size_t)(k0 + bro + 8)  * N + bco);
            bv3 = *(const float4*)(Bp + (size_t)(k0 + bro + 12) * N + bco);
        }
    };
    auto STORE = [&](int buf) {
        As[buf][ak + 0][arow] = a0.x; As[buf][ak + 1][arow] = a0.y;
        As[buf][ak + 2][arow] = a0.z; As[buf][ak + 3][arow] = a0.w;
        As[buf][ak + 4][arow] = a1.x; As[buf][ak + 5][arow] = a1.y;
        As[buf][ak + 6][arow] = a1.z; As[buf][ak + 7][arow] = a1.w;
        if (TRANSB) {
            Bs[buf][ 0][tid] = bv0.x; Bs[buf][ 1][tid] = bv0.y;
            Bs[buf][ 2][tid] = bv0.z; Bs[buf][ 3][tid] = bv0.w;
            Bs[buf][ 4][tid] = bv1.x; Bs[buf][ 5][tid] = bv1.y;
            Bs[buf][ 6][tid] = bv1.z; Bs[buf][ 7][tid] = bv1.w;
            Bs[buf][ 8][tid] = bv2.x; Bs[buf][ 9][tid] = bv2.y;
            Bs[buf][10][tid] = bv2.z; Bs[buf][11][tid] = bv2.w;
            Bs[buf][12][tid] = bv3.x; Bs[buf][13][tid] = bv3.y;
            Bs[buf][14][tid] = bv3.z; Bs[buf][15][tid] = bv3.w;
        } else {
            *(float4*)&Bs[buf][bro + 0 ][bco] = bv0;
            *(float4*)&Bs[buf][bro + 4 ][bco] = bv1;
            *(float4*)&Bs[buf][bro + 8 ][bco] = bv2;
            *(float4*)&Bs[buf][bro + 12][bco] = bv3;
        }
    };
    auto COMPUTE = [&](int buf) {
        #pragma unroll
        for (int kk = 0; kk < 16; ++kk) {
            float4 av0 = *(const float4*)&As[buf][kk][ty * 4];
            float4 av1 = *(const float4*)&As[buf][kk][64 + ty * 4];
            ulonglong2 c0 = *(const ulonglong2*)&Bs[buf][kk][tx * 4];
            ulonglong2 c1 = *(const ulonglong2*)&Bs[buf][kk][64 + tx * 4];
            ulonglong2 c2 = *(const ulonglong2*)&Bs[buf][kk][128 + tx * 4];
            ulonglong2 c3 = *(const ulonglong2*)&Bs[buf][kk][192 + tx * 4];
            unsigned long long bB[8] = { c0.x, c0.y, c1.x, c1.y,
                                         c2.x, c2.y, c3.x, c3.y };
            unsigned long long ap[8] = {
                pack2(av0.x), pack2(av0.y), pack2(av0.z), pack2(av0.w),
                pack2(av1.x), pack2(av1.y), pack2(av1.z), pack2(av1.w) };
            #pragma unroll
            for (int i = 0; i < 8; ++i) {
                #pragma unroll
                for (int j = 0; j < 8; ++j)
                    acc[i][j] = ffma2(ap[i], bB[j], acc[i][j]);
            }
        }
    };

    // ---- pipelined mainloop: one __syncthreads per k-iteration ----
    LOAD(0);
    STORE(0);
    __syncthreads();
    int buf = 0;
    for (int k0 = 16; k0 < K; k0 += 16) {
        LOAD(k0);          // prefetch next tile (latency hidden by COMPUTE)
        COMPUTE(buf);
        STORE(buf ^ 1);
        __syncthreads();
        buf ^= 1;
    }
    COMPUTE(buf);

    // ---- epilogue: 4 float4 stores per m-row (n chunks at stride 64) ----
    #pragma unroll
    for (int i = 0; i < 8; ++i) {
        int row = (i < 4) ? (ty * 4 + i) : (64 + ty * 4 + (i - 4));
        size_t base = (size_t)row * N;
        #pragma unroll
        for (int c = 0; c < 4; ++c) {
            float2 plo = unpack2(acc[i][2 * c]);
            float2 phi = unpack2(acc[i][2 * c + 1]);
            float4 o = make_float4(plo.x * alpha, plo.y * alpha,
                                   phi.x * alpha, phi.y * alpha);
            size_t off = base + c * 64 + tx * 4;
            if (ADD_RES) {
                float4 r = *(const float4*)(Rp + off);
                o.x += r.x; o.y += r.y; o.z += r.z; o.w += r.w;
            }
            *(float4*)(Cp + off) = o;
        }
    }
}

// -------- softmax over the BATCH axis: one thread per (q,k) pair --------
__global__ __launch_bounds__(256) void softmax_batch_kernel() {
    int idx = blockIdx.x * 256 + threadIdx.x;     // < S_*S_
    float v[B_];
    float m = -3.4e38f;
    #pragma unroll
    for (int b = 0; b < B_; ++b) {
        v[b] = g_sc[(size_t)b * (S_ * S_) + idx];
        m = fmaxf(m, v[b]);
    }
    float s = 0.f;
    #pragma unroll
    for (int b = 0; b < B_; ++b) {
        v[b] = expf(v[b] - m);
        s += v[b];
    }
    float inv = 1.0f / s;
    #pragma unroll
    for (int b = 0; b < B_; ++b)
        g_sc[(size_t)b * (S_ * S_) + idx] = v[b] * inv;
}

extern "C" void kernel_launch(void* const* d_in, const int* in_sizes, int n_in,
                              void* d_out, int out_size) {
    const float* x = (const float*)d_in[0];
    const float* Q = (const float*)d_in[1];
    const float* K = (const float*)d_in[2];
    const float* V = (const float*)d_in[3];
    float* out = (float*)d_out;

    float *xn, *q, *k, *v, *sc;
    cudaGetSymbolAddress((void**)&xn, g_xn);
    cudaGetSymbolAddress((void**)&q,  g_q);
    cudaGetSymbolAddress((void**)&k,  g_k);
    cudaGetSymbolAddress((void**)&v,  g_v);
    cudaGetSymbolAddress((void**)&sc, g_sc);

    // 1) BatchNorm stats (per channel over B*S)
    bn_stats_kernel<<<C_, 256>>>(x);

    // 2) normalize + transpose -> xn [B,S,C]
    normalize_kernel<<<dim3(S_ / 32, C_ / 32, B_), dim3(32, 8)>>>(x);

    // 3) q/k/v = xn @ {Q,K,V}   [16384,512] x [512,512]
    dim3 g1(C_ / 256, BS_ / 128, 1);
    gemm_kernel<false, false><<<g1, 256>>>(xn, Q, q, nullptr, BS_, C_, C_, 0, 0, 0, 1.0f);
    gemm_kernel<false, false><<<g1, 256>>>(xn, K, k, nullptr, BS_, C_, C_, 0, 0, 0, 1.0f);
    gemm_kernel<false, false><<<g1, 256>>>(xn, V, v, nullptr, BS_, C_, C_, 0, 0, 0, 1.0f);

    // 4) scores[b] = (q[b] @ k[b]^T) / sqrt(C)   (NT, batched)
    dim3 g2(S_ / 256, S_ / 128, B_);
    gemm_kernel<true, false><<<g2, 256>>>(q, k, sc, nullptr, S_, S_, C_,
                                          (size_t)S_ * C_, (size_t)S_ * C_,
                                          (size_t)S_ * S_, 0.04419417382415922f);

    // 5) softmax over batch axis (Softmax2d quirk)
    softmax_batch_kernel<<<(S_ * S_) / 256, 256>>>();

    // 6) out[b] = attn_w[b] @ v[b] + xn[b]   (NN, batched, fused residual)
    dim3 g3(C_ / 256, S_ / 128, B_);
    gemm_kernel<false, true><<<g3, 256>>>(sc, v, out, xn, S_, C_, S_,
                                          (size_t)S_ * S_, (size_t)S_ * C_,
                                          (size_t)S_ * C_, 1.0f);
}

// round 10
// speedup vs baseline: 1.7390x; 1.5045x over previous
#include <cuda_runtime.h>
#include <cuda_bf16.h>
#include <cstdint>

// Problem: x[16,512,32,32], Q/K/V[512,512]
#define B_ 16
#define C_ 512
#define S_ 1024
#define BS_ (B_ * S_)   // 16384

typedef __nv_bfloat16 bf16;

// ---------------- device scratch ----------------
__device__ float g_xn[BS_ * C_];          // normalized x (residual)
__device__ float g_sc[B_ * S_ * S_];      // scores fp32 [B][q][k]
__device__ float g_mean[C_], g_rsig[C_];

#define PAIR(name, n) \
  __device__ __align__(16) bf16 name##h[n]; \
  __device__ __align__(16) bf16 name##l[n]
PAIR(g_xb, BS_ * C_);      // xn split      [s][c]
PAIR(g_qw, C_ * C_);       // Q^T split     [d][c]
PAIR(g_kw, C_ * C_);       // K^T split
PAIR(g_vw, C_ * C_);       // V^T split
PAIR(g_qb, BS_ * C_);      // q split       [b*S+s][c]
PAIR(g_kb, BS_ * C_);      // k split
PAIR(g_vt, C_ * BS_);      // v^T split     [c][b*S+s]
PAIR(g_wt, B_ * S_ * S_);  // attn weights  [b][q][j]

// ---------------- helpers ----------------
__device__ __forceinline__ void split2(float x, bf16& h, bf16& l) {
    h = __float2bfloat16(x);
    l = __float2bfloat16(x - __bfloat162float(h));
}
__device__ __forceinline__ uint32_t smem_u32(const void* p) {
    return (uint32_t)__cvta_generic_to_shared(p);
}
__device__ __forceinline__ void cp16(uint32_t dst, const void* src) {
    asm volatile("cp.async.cg.shared.global [%0], [%1], 16;" :: "r"(dst), "l"(src));
}
__device__ __forceinline__ void ldsm4(uint32_t& r0, uint32_t& r1,
                                      uint32_t& r2, uint32_t& r3, uint32_t a) {
    asm volatile("ldmatrix.sync.aligned.m8n8.x4.shared.b16 {%0,%1,%2,%3}, [%4];"
                 : "=r"(r0), "=r"(r1), "=r"(r2), "=r"(r3) : "r"(a));
}
__device__ __forceinline__ void mma16816(float* d, const uint32_t* a,
                                         uint32_t b0, uint32_t b1) {
    asm volatile(
        "mma.sync.aligned.m16n8k16.row.col.f32.bf16.bf16.f32 "
        "{%0,%1,%2,%3}, {%4,%5,%6,%7}, {%8,%9}, {%0,%1,%2,%3};"
        : "+f"(d[0]), "+f"(d[1]), "+f"(d[2]), "+f"(d[3])
        : "r"(a[0]), "r"(a[1]), "r"(a[2]), "r"(a[3]), "r"(b0), "r"(b1));
}

// ---------------- BatchNorm stats ----------------
__global__ __launch_bounds__(256) void bn_stats_kernel(const float* __restrict__ x) {
    int c = blockIdx.x, t = threadIdx.x;
    float s = 0.f, ss = 0.f;
    for (int b = 0; b < B_; ++b) {
        const float* p = x + ((size_t)b * C_ + c) * S_;
        for (int i = t; i < S_; i += 256) { float v = p[i]; s += v; ss += v * v; }
    }
    #pragma unroll
    for (int o = 16; o > 0; o >>= 1) {
        s  += __shfl_down_sync(0xffffffffu, s,  o);
        ss += __shfl_down_sync(0xffffffffu, ss, o);
    }
    __shared__ float shs[8], shq[8];
    int w = t >> 5, l = t & 31;
    if (l == 0) { shs[w] = s; shq[w] = ss; }
    __syncthreads();
    if (t == 0) {
        float S = 0.f, Qq = 0.f;
        #pragma unroll
        for (int i = 0; i < 8; ++i) { S += shs[i]; Qq += shq[i]; }
        const float invN = 1.0f / (float)BS_;
        float mu = S * invN;
        g_mean[c] = mu;
        g_rsig[c] = rsqrtf(Qq * invN - mu * mu + 1e-5f);
    }
}

// ---------- normalize + transpose: fp32 xn AND bf16 split pair ----------
__global__ __launch_bounds__(256) void normalize_kernel(const float* __restrict__ x) {
    __shared__ float tile[32][33];
    int b = blockIdx.z, c0 = blockIdx.y * 32, s0 = blockIdx.x * 32;
    int tx = threadIdx.x, ty = threadIdx.y;
    #pragma unroll
    for (int r = 0; r < 4; ++r)
        tile[ty + 8 * r][tx] = x[((size_t)b * C_ + c0 + ty + 8 * r) * S_ + s0 + tx];
    __syncthreads();
    float mu = g_mean[c0 + tx], rs = g_rsig[c0 + tx];
    #pragma unroll
    for (int r = 0; r < 4; ++r) {
        int s = s0 + ty + 8 * r;
        size_t idx = ((size_t)b * S_ + s) * C_ + c0 + tx;
        float v = (tile[tx][ty + 8 * r] - mu) * rs;
        g_xn[idx] = v;
        split2(v, g_xbh[idx], g_xbl[idx]);
    }
}

// ---------- weight transpose + split: out[n][k] = in[k][n] ----------
__global__ __launch_bounds__(256) void wsplit_kernel(
    const float* __restrict__ in, bf16* __restrict__ oh, bf16* __restrict__ ol)
{
    __shared__ float t[32][33];
    int n0 = blockIdx.x * 32, k0 = blockIdx.y * 32;
    int tx = threadIdx.x, ty = threadIdx.y;
    #pragma unroll
    for (int r = 0; r < 4; ++r)
        t[ty + 8 * r][tx] = in[(size_t)(k0 + ty + 8 * r) * C_ + n0 + tx];
    __syncthreads();
    #pragma unroll
    for (int r = 0; r < 4; ++r) {
        size_t idx = (size_t)(n0 + ty + 8 * r) * C_ + k0 + tx;
        split2(t[tx][ty + 8 * r], oh[idx], ol[idx]);
    }
}

// ---------------------------------------------------------------------------
// Split-2 bf16 HMMA GEMM: D[m][n] = alpha * sum_k A[m][k]*B[n][k]
// A,B bf16 (hi,lo) K-major. CTA 128x128, 8 warps of 64x32, K-chunk 16,
// cp.async double buffer, padded smem rows (24 bf16) -> conflict-free ldmatrix.
// EPI: 0 = split-2 bf16 out; 2 = fp32*alpha; 3 = fp32 + residual.
// ---------------------------------------------------------------------------
#define LDS_T 24
#define TILE_BYTES (128 * LDS_T * 2)      // 6144
#define BUF_BYTES  (4 * TILE_BYTES)       // 24576

template <int EPI>
__global__ __launch_bounds__(256, 2) void mma_gemm(
    const bf16* __restrict__ Ah, const bf16* __restrict__ Al, size_t sAz, int lda,
    const bf16* __restrict__ Bh, const bf16* __restrict__ Bl, size_t sBz, int ldb,
    int K, float alpha,
    float* __restrict__ outF, const float* __restrict__ resid, size_t sOz, int ldO,
    bf16* __restrict__ Oh, bf16* __restrict__ Ol)
{
    __shared__ bf16 sm[2][4][128][LDS_T];   // buf, tile(Ah,Al,Bh,Bl), row, k

    const int tid = threadIdx.x, lane = tid & 31, w = tid >> 5;
    const int m0 = blockIdx.y * 128, n0 = blockIdx.x * 128, z = blockIdx.z;
    const int warp_m = (w >> 2) * 64, warp_n = (w & 3) * 32;

    const bf16* srcs[4] = { Ah + z * sAz, Al + z * sAz,
                            Bh + z * sBz, Bl + z * sBz };
    // loader: 64 threads per tile, 2 rows each, 2x 16B per row
    const int ltile = tid >> 6;
    const int lrow  = (tid & 63) * 2;
    const bf16* lsrc = srcs[ltile] +
        (size_t)((ltile < 2 ? m0 : n0) + lrow) * (ltile < 2 ? lda : ldb);
    const int lld = (ltile < 2 ? lda : ldb);
    const uint32_t ldst = smem_u32(&sm[0][ltile][lrow][0]);

    auto ISSUE = [&](int kc, int buf) {
        uint32_t d = ldst + buf * BUF_BYTES;
        const bf16* s0 = lsrc + kc;
        cp16(d,                    s0);
        cp16(d + 16,               s0 + 8);
        cp16(d + LDS_T * 2,        s0 + lld);
        cp16(d + LDS_T * 2 + 16,   s0 + lld + 8);
        asm volatile("cp.async.commit_group;");
    };

    // ldmatrix lane offsets (bf16 units)
    const uint32_t aoff = (uint32_t)((warp_m + (lane & 15)) * LDS_T + (lane >> 4) * 8);
    const uint32_t boff = (uint32_t)((warp_n + ((lane >> 4) & 1) * 8 + (lane & 7)) * LDS_T
                                     + ((lane >> 3) & 1) * 8);
    const uint32_t smb = smem_u32(sm);

    float acc[4][4][4];
    #pragma unroll
    for (int i = 0; i < 4; ++i)
        #pragma unroll
        for (int j = 0; j < 4; ++j)
            #pragma unroll
            for (int q = 0; q < 4; ++q) acc[i][j][q] = 0.f;

    const int nch = K >> 4;
    ISSUE(0, 0);
    for (int t = 0; t < nch; ++t) {
        const int buf = t & 1;
        if (t + 1 < nch) {
            ISSUE((t + 1) << 4, buf ^ 1);
            asm volatile("cp.async.wait_group 1;");
        } else {
            asm volatile("cp.async.wait_group 0;");
        }
        __syncthreads();

        const uint32_t base = smb + buf * BUF_BYTES;
        uint32_t bh[8], bl[8];
        #pragma unroll
        for (int ni = 0; ni < 2; ++ni) {
            uint32_t ba = base + 2 * TILE_BYTES + (boff + ni * 16 * LDS_T) * 2;
            ldsm4(bh[4 * ni], bh[4 * ni + 1], bh[4 * ni + 2], bh[4 * ni + 3], ba);
            ldsm4(bl[4 * ni], bl[4 * ni + 1], bl[4 * ni + 2], bl[4 * ni + 3],
                  ba + TILE_BYTES);
        }
        #pragma unroll
        for (int mi = 0; mi < 4; ++mi) {
            uint32_t aa = base + (aoff + mi * 16 * LDS_T) * 2;
            uint32_t ah[4], al[4];
            ldsm4(ah[0], ah[1], ah[2], ah[3], aa);
            ldsm4(al[0], al[1], al[2], al[3], aa + TILE_BYTES);
            #pragma unroll
            for (int nj = 0; nj < 4; ++nj) {
                mma16816(acc[mi][nj], ah, bh[2 * nj], bh[2 * nj + 1]);
                mma16816(acc[mi][nj], ah, bl[2 * nj], bl[2 * nj + 1]);
                mma16816(acc[mi][nj], al, bh[2 * nj], bh[2 * nj + 1]);
            }
        }
        __syncthreads();   // all warps done with buf before it is refilled
    }

    // ---- epilogue ----
    const int g  = lane >> 2;
    const int t4 = lane & 3;
    #pragma unroll
    for (int mi = 0; mi < 4; ++mi) {
        #pragma unroll
        for (int nj = 0; nj < 4; ++nj) {
            int row = m0 + warp_m + mi * 16 + g;
            int col = n0 + warp_n + nj * 8 + 2 * t4;
            #pragma unroll
            for (int h = 0; h < 2; ++h) {      // h=0: rows g, h=1: rows g+8
                int r = row + 8 * h;
                float v0 = acc[mi][nj][2 * h]     * alpha;
                float v1 = acc[mi][nj][2 * h + 1] * alpha;
                size_t off = z * sOz + (size_t)r * ldO + col;
                if (EPI == 0) {
                    bf16 h0, l0, h1, l1;
                    split2(v0, h0, l0);
                    split2(v1, h1, l1);
                    *(__nv_bfloat162*)(Oh + (size_t)r * ldO + col) =
                        __nv_bfloat162(h0, h1);
                    *(__nv_bfloat162*)(Ol + (size_t)r * ldO + col) =
                        __nv_bfloat162(l0, l1);
                } else if (EPI == 2) {
                    *(float2*)(outF + off) = make_float2(v0, v1);
                } else {
                    float2 rr = *(const float2*)(resid + off);
                    *(float2*)(outF + off) = make_float2(v0 + rr.x, v1 + rr.y);
                }
            }
        }
    }
}

// -------- softmax over BATCH axis + split-2 weights --------
__global__ __launch_bounds__(256) void softmax_batch_kernel() {
    int idx = blockIdx.x * 256 + threadIdx.x;   // < S_*S_
    float v[B_];
    float m = -3.4e38f;
    #pragma unroll
    for (int b = 0; b < B_; ++b) {
        v[b] = g_sc[(size_t)b * (S_ * S_) + idx];
        m = fmaxf(m, v[b]);
    }
    float s = 0.f;
    #pragma unroll
    for (int b = 0; b < B_; ++b) { v[b] = expf(v[b] - m); s += v[b]; }
    float inv = 1.0f / s;
    #pragma unroll
    for (int b = 0; b < B_; ++b) {
        size_t o = (size_t)b * (S_ * S_) + idx;
        split2(v[b] * inv, g_wth[o], g_wtl[o]);
    }
}

extern "C" void kernel_launch(void* const* d_in, const int* in_sizes, int n_in,
                              void* d_out, int out_size) {
    const float* x = (const float*)d_in[0];
    const float* Q = (const float*)d_in[1];
    const float* K = (const float*)d_in[2];
    const float* V = (const float*)d_in[3];
    float* out = (float*)d_out;

    float *xn, *sc;
    cudaGetSymbolAddress((void**)&xn, g_xn);
    cudaGetSymbolAddress((void**)&sc, g_sc);
    #define GET2(var, name) \
        bf16 *var##h, *var##l; \
        cudaGetSymbolAddress((void**)&var##h, name##h); \
        cudaGetSymbolAddress((void**)&var##l, name##l)
    GET2(xb, g_xb); GET2(qw, g_qw); GET2(kw, g_kw); GET2(vw, g_vw);
    GET2(qb, g_qb); GET2(kb, g_kb); GET2(vt, g_vt); GET2(wt, g_wt);

    // 1-2) BN stats + normalize/split
    bn_stats_kernel<<<C_, 256>>>(x);
    normalize_kernel<<<dim3(S_ / 32, C_ / 32, B_), dim3(32, 8)>>>(x);

    // 3) weight transpose + split
    dim3 wg(16, 16), wb(32, 8);
    wsplit_kernel<<<wg, wb>>>(Q, qwh, qwl);
    wsplit_kernel<<<wg, wb>>>(K, kwh, kwl);
    wsplit_kernel<<<wg, wb>>>(V, vwh, vwl);

    // 4) q = xn@Q, k = xn@K: D[s][d], M=BS, N=C, K=C
    dim3 gq(C_ / 128, BS_ / 128, 1);
    mma_gemm<0><<<gq, 256>>>(xbh, xbl, 0, C_, qwh, qwl, 0, C_,
                             C_, 1.0f, nullptr, nullptr, 0, C_, qbh, qbl);
    mma_gemm<0><<<gq, 256>>>(xbh, xbl, 0, C_, kwh, kwl, 0, C_,
                             C_, 1.0f, nullptr, nullptr, 0, C_, kbh, kbl);
    // vT[c][s] = sum_k V^T[c][k]*xn[s][k]: M=C, N=BS
    dim3 gv(BS_ / 128, C_ / 128, 1);
    mma_gemm<0><<<gv, 256>>>(vwh, vwl, 0, C_, xbh, xbl, 0, C_,
                             C_, 1.0f, nullptr, nullptr, 0, BS_, vth, vtl);

    // 5) scores[b][q][k'] = (q.k')/sqrt(C), fp32: M=N=S, K=C, batched
    dim3 gs(S_ / 128, S_ / 128, B_);
    mma_gemm<2><<<gs, 256>>>(qbh, qbl, (size_t)S_ * C_, C_,
                             kbh, kbl, (size_t)S_ * C_, C_,
                             C_, 0.04419417382415922f,
                             sc, nullptr, (size_t)S_ * S_, S_, nullptr, nullptr);

    // 6) batch softmax + split W
    softmax_batch_kernel<<<(S_ * S_) / 256, 256>>>();

    // 7) out[b][s][c] = sum_j W[b][s][j]*vT[c][b*S+j] + xn: M=S, N=C, K=S
    dim3 ga(C_ / 128, S_ / 128, B_);
    mma_gemm<3><<<ga, 256>>>(wth, wtl, (size_t)S_ * S_, S_,
                             vth, vtl, (size_t)S_, BS_,
                             S_, 1.0f,
                             out, xn, (size_t)S_ * C_, C_, nullptr, nullptr);
}

// round 11
// speedup vs baseline: 2.0275x; 1.1659x over previous
#include <cuda_runtime.h>
#include <cuda_bf16.h>
#include <cstdint>

// Problem: x[16,512,32,32], Q/K/V[512,512]
#define B_ 16
#define C_ 512
#define S_ 1024
#define BS_ (B_ * S_)   // 16384

typedef __nv_bfloat16 bf16;

// ---------------- device scratch ----------------
__device__ float g_xn[BS_ * C_];          // normalized x (residual)
__device__ float g_sc[B_ * S_ * S_];      // scores fp32 [B][q][k]
__device__ float g_mean[C_], g_rsig[C_];

#define PAIR(name, n) \
  __device__ __align__(16) bf16 name##h[n]; \
  __device__ __align__(16) bf16 name##l[n]
PAIR(g_xb, BS_ * C_);      // xn split      [s][c]
PAIR(g_qw, C_ * C_);       // Q^T split     [d][c]
PAIR(g_kw, C_ * C_);       // K^T split
PAIR(g_vw, C_ * C_);       // V^T split
PAIR(g_qb, BS_ * C_);      // q split       [b*S+s][c]
PAIR(g_kb, BS_ * C_);      // k split
PAIR(g_vt, C_ * BS_);      // v^T split     [c][b*S+s]
PAIR(g_wt, B_ * S_ * S_);  // attn weights  [b][q][j]

// ---------------- helpers ----------------
__device__ __forceinline__ void split2(float x, bf16& h, bf16& l) {
    h = __float2bfloat16(x);
    l = __float2bfloat16(x - __bfloat162float(h));
}
__device__ __forceinline__ uint32_t smem_u32(const void* p) {
    return (uint32_t)__cvta_generic_to_shared(p);
}
__device__ __forceinline__ void cp16(uint32_t dst, const void* src) {
    asm volatile("cp.async.cg.shared.global [%0], [%1], 16;" :: "r"(dst), "l"(src));
}
__device__ __forceinline__ void ldsm4(uint32_t& r0, uint32_t& r1,
                                      uint32_t& r2, uint32_t& r3, uint32_t a) {
    asm volatile("ldmatrix.sync.aligned.m8n8.x4.shared.b16 {%0,%1,%2,%3}, [%4];"
                 : "=r"(r0), "=r"(r1), "=r"(r2), "=r"(r3) : "r"(a));
}
__device__ __forceinline__ void mma16816(float* d, const uint32_t* a,
                                         uint32_t b0, uint32_t b1) {
    asm volatile(
        "mma.sync.aligned.m16n8k16.row.col.f32.bf16.bf16.f32 "
        "{%0,%1,%2,%3}, {%4,%5,%6,%7}, {%8,%9}, {%0,%1,%2,%3};"
        : "+f"(d[0]), "+f"(d[1]), "+f"(d[2]), "+f"(d[3])
        : "r"(a[0]), "r"(a[1]), "r"(a[2]), "r"(a[3]), "r"(b0), "r"(b1));
}

// ---------------- BatchNorm stats ----------------
__global__ __launch_bounds__(256) void bn_stats_kernel(const float* __restrict__ x) {
    int c = blockIdx.x, t = threadIdx.x;
    float s = 0.f, ss = 0.f;
    for (int b = 0; b < B_; ++b) {
        const float* p = x + ((size_t)b * C_ + c) * S_;
        for (int i = t; i < S_; i += 256) { float v = p[i]; s += v; ss += v * v; }
    }
    #pragma unroll
    for (int o = 16; o > 0; o >>= 1) {
        s  += __shfl_down_sync(0xffffffffu, s,  o);
        ss += __shfl_down_sync(0xffffffffu, ss, o);
    }
    __shared__ float shs[8], shq[8];
    int w = t >> 5, l = t & 31;
    if (l == 0) { shs[w] = s; shq[w] = ss; }
    __syncthreads();
    if (t == 0) {
        float S = 0.f, Qq = 0.f;
        #pragma unroll
        for (int i = 0; i < 8; ++i) { S += shs[i]; Qq += shq[i]; }
        const float invN = 1.0f / (float)BS_;
        float mu = S * invN;
        g_mean[c] = mu;
        g_rsig[c] = rsqrtf(Qq * invN - mu * mu + 1e-5f);
    }
}

// ---------- normalize + transpose: fp32 xn AND bf16 split pair ----------
__global__ __launch_bounds__(256) void normalize_kernel(const float* __restrict__ x) {
    __shared__ float tile[32][33];
    int b = blockIdx.z, c0 = blockIdx.y * 32, s0 = blockIdx.x * 32;
    int tx = threadIdx.x, ty = threadIdx.y;
    #pragma unroll
    for (int r = 0; r < 4; ++r)
        tile[ty + 8 * r][tx] = x[((size_t)b * C_ + c0 + ty + 8 * r) * S_ + s0 + tx];
    __syncthreads();
    float mu = g_mean[c0 + tx], rs = g_rsig[c0 + tx];
    #pragma unroll
    for (int r = 0; r < 4; ++r) {
        int s = s0 + ty + 8 * r;
        size_t idx = ((size_t)b * S_ + s) * C_ + c0 + tx;
        float v = (tile[tx][ty + 8 * r] - mu) * rs;
        g_xn[idx] = v;
        split2(v, g_xbh[idx], g_xbl[idx]);
    }
}

// ---------- weight transpose + split: out[n][k] = in[k][n] ----------
__global__ __launch_bounds__(256) void wsplit_kernel(
    const float* __restrict__ in, bf16* __restrict__ oh, bf16* __restrict__ ol)
{
    __shared__ float t[32][33];
    int n0 = blockIdx.x * 32, k0 = blockIdx.y * 32;
    int tx = threadIdx.x, ty = threadIdx.y;
    #pragma unroll
    for (int r = 0; r < 4; ++r)
        t[ty + 8 * r][tx] = in[(size_t)(k0 + ty + 8 * r) * C_ + n0 + tx];
    __syncthreads();
    #pragma unroll
    for (int r = 0; r < 4; ++r) {
        size_t idx = (size_t)(n0 + ty + 8 * r) * C_ + k0 + tx;
        split2(t[tx][ty + 8 * r], oh[idx], ol[idx]);
    }
}

// ---------------------------------------------------------------------------
// Split-2 bf16 HMMA GEMM: D[m][n] = alpha * sum_k A[m][k]*B[n][k]
// A,B bf16 (hi,lo) K-major. CTA 128x128, 4 warps of 64x64, K-chunk 16,
// cp.async double buffer, ONE __syncthreads per chunk, padded smem rows.
// EPI: 0 = split-2 bf16 out; 2 = fp32*alpha; 3 = fp32 + residual.
// ---------------------------------------------------------------------------
#define LDS_T 24
#define TILE_BYTES (128 * LDS_T * 2)      // 6144
#define BUF_BYTES  (4 * TILE_BYTES)       // 24576

template <int EPI>
__global__ __launch_bounds__(128, 2) void mma_gemm(
    const bf16* __restrict__ Ah, const bf16* __restrict__ Al, size_t sAz, int lda,
    const bf16* __restrict__ Bh, const bf16* __restrict__ Bl, size_t sBz, int ldb,
    int K, float alpha,
    float* __restrict__ outF, const float* __restrict__ resid, size_t sOz, int ldO,
    bf16* __restrict__ Oh, bf16* __restrict__ Ol)
{
    __shared__ bf16 sm[2][4][128][LDS_T];   // buf, tile(Ah,Al,Bh,Bl), row, k

    const int tid = threadIdx.x, lane = tid & 31, w = tid >> 5;   // w: 0..3
    const int m0 = blockIdx.y * 128, n0 = blockIdx.x * 128, z = blockIdx.z;
    const int warp_m = (w >> 1) * 64, warp_n = (w & 1) * 64;

    // loader: warp w owns tile w (Ah, Al, Bh, Bl); 4 rows/lane, 32B/row
    const bf16* srcs[4] = { Ah + z * sAz, Al + z * sAz,
                            Bh + z * sBz, Bl + z * sBz };
    const int lld  = (w < 2) ? lda : ldb;
    const bf16* lsrc = srcs[w] + (size_t)((w < 2 ? m0 : n0) + lane) * lld;
    const uint32_t ldst = smem_u32(&sm[0][w][lane][0]);

    auto ISSUE = [&](int kc, int buf) {
        uint32_t d = ldst + buf * BUF_BYTES;
        const bf16* s0 = lsrc + kc;
        #pragma unroll
        for (int r = 0; r < 4; ++r) {
            cp16(d + r * (32 * LDS_T * 2),      s0 + (size_t)(32 * r) * lld);
            cp16(d + r * (32 * LDS_T * 2) + 16, s0 + (size_t)(32 * r) * lld + 8);
        }
        asm volatile("cp.async.commit_group;");
    };

    // ldmatrix lane offsets (bf16 units) — proven layout from R10 kernel
    const uint32_t aoff = (uint32_t)((warp_m + (lane & 15)) * LDS_T + (lane >> 4) * 8);
    const uint32_t boff = (uint32_t)((warp_n + ((lane >> 4) & 1) * 8 + (lane & 7)) * LDS_T
                                     + ((lane >> 3) & 1) * 8);
    const uint32_t smb = smem_u32(sm);

    float acc[4][8][4];
    #pragma unroll
    for (int i = 0; i < 4; ++i)
        #pragma unroll
        for (int j = 0; j < 8; ++j)
            #pragma unroll
            for (int q = 0; q < 4; ++q) acc[i][j][q] = 0.f;

    const int nch = K >> 4;
    ISSUE(0, 0);
    for (int t = 0; t < nch; ++t) {
        const int buf = t & 1;
        asm volatile("cp.async.wait_group 0;");
        __syncthreads();                       // chunk t visible; buf^1 free
        if (t + 1 < nch) ISSUE((t + 1) << 4, buf ^ 1);

        const uint32_t base = smb + buf * BUF_BYTES;
        uint32_t bh[16], bl[16];
        #pragma unroll
        for (int ni = 0; ni < 4; ++ni) {
            uint32_t ba = base + 2 * TILE_BYTES + (boff + ni * 16 * LDS_T) * 2;
            ldsm4(bh[4 * ni], bh[4 * ni + 1], bh[4 * ni + 2], bh[4 * ni + 3], ba);
            ldsm4(bl[4 * ni], bl[4 * ni + 1], bl[4 * ni + 2], bl[4 * ni + 3],
                  ba + TILE_BYTES);
        }
        #pragma unroll
        for (int mi = 0; mi < 4; ++mi) {
            uint32_t aa = base + (aoff + mi * 16 * LDS_T) * 2;
            uint32_t ah[4], al[4];
            ldsm4(ah[0], ah[1], ah[2], ah[3], aa);
            ldsm4(al[0], al[1], al[2], al[3], aa + TILE_BYTES);
            #pragma unroll
            for (int nj = 0; nj < 8; ++nj) {
                mma16816(acc[mi][nj], ah, bh[2 * nj], bh[2 * nj + 1]);
                mma16816(acc[mi][nj], ah, bl[2 * nj], bl[2 * nj + 1]);
                mma16816(acc[mi][nj], al, bh[2 * nj], bh[2 * nj + 1]);
            }
        }
    }

    // ---- epilogue ----
    const int g  = lane >> 2;
    const int t4 = lane & 3;
    #pragma unroll
    for (int mi = 0; mi < 4; ++mi) {
        #pragma unroll
        for (int nj = 0; nj < 8; ++nj) {
            int row = m0 + warp_m + mi * 16 + g;
            int col = n0 + warp_n + nj * 8 + 2 * t4;
            #pragma unroll
            for (int h = 0; h < 2; ++h) {      // h=0: rows g, h=1: rows g+8
                int r = row + 8 * h;
                float v0 = acc[mi][nj][2 * h]     * alpha;
                float v1 = acc[mi][nj][2 * h + 1] * alpha;
                size_t off = z * sOz + (size_t)r * ldO + col;
                if (EPI == 0) {
                    bf16 h0, l0, h1, l1;
                    split2(v0, h0, l0);
                    split2(v1, h1, l1);
                    *(__nv_bfloat162*)(Oh + (size_t)r * ldO + col) =
                        __nv_bfloat162(h0, h1);
                    *(__nv_bfloat162*)(Ol + (size_t)r * ldO + col) =
                        __nv_bfloat162(l0, l1);
                } else if (EPI == 2) {
                    *(float2*)(outF + off) = make_float2(v0, v1);
                } else {
                    float2 rr = *(const float2*)(resid + off);
                    *(float2*)(outF + off) = make_float2(v0 + rr.x, v1 + rr.y);
                }
            }
        }
    }
}

// -------- softmax over BATCH axis + split-2 weights --------
__global__ __launch_bounds__(256) void softmax_batch_kernel() {
    int idx = blockIdx.x * 256 + threadIdx.x;   // < S_*S_
    float v[B_];
    float m = -3.4e38f;
    #pragma unroll
    for (int b = 0; b < B_; ++b) {
        v[b] = g_sc[(size_t)b * (S_ * S_) + idx];
        m = fmaxf(m, v[b]);
    }
    float s = 0.f;
    #pragma unroll
    for (int b = 0; b < B_; ++b) { v[b] = expf(v[b] - m); s += v[b]; }
    float inv = 1.0f / s;
    #pragma unroll
    for (int b = 0; b < B_; ++b) {
        size_t o = (size_t)b * (S_ * S_) + idx;
        split2(v[b] * inv, g_wth[o], g_wtl[o]);
    }
}

extern "C" void kernel_launch(void* const* d_in, const int* in_sizes, int n_in,
                              void* d_out, int out_size) {
    const float* x = (const float*)d_in[0];
    const float* Q = (const float*)d_in[1];
    const float* K = (const float*)d_in[2];
    const float* V = (const float*)d_in[3];
    float* out = (float*)d_out;

    float *xn, *sc;
    cudaGetSymbolAddress((void**)&xn, g_xn);
    cudaGetSymbolAddress((void**)&sc, g_sc);
    #define GET2(var, name) \
        bf16 *var##h, *var##l; \
        cudaGetSymbolAddress((void**)&var##h, name##h); \
        cudaGetSymbolAddress((void**)&var##l, name##l)
    GET2(xb, g_xb); GET2(qw, g_qw); GET2(kw, g_kw); GET2(vw, g_vw);
    GET2(qb, g_qb); GET2(kb, g_kb); GET2(vt, g_vt); GET2(wt, g_wt);

    // 1-2) BN stats + normalize/split
    bn_stats_kernel<<<C_, 256>>>(x);
    normalize_kernel<<<dim3(S_ / 32, C_ / 32, B_), dim3(32, 8)>>>(x);

    // 3) weight transpose + split
    dim3 wg(16, 16), wb(32, 8);
    wsplit_kernel<<<wg, wb>>>(Q, qwh, qwl);
    wsplit_kernel<<<wg, wb>>>(K, kwh, kwl);
    wsplit_kernel<<<wg, wb>>>(V, vwh, vwl);

    // 4) q = xn@Q, k = xn@K: D[s][d], M=BS, N=C, K=C
    dim3 gq(C_ / 128, BS_ / 128, 1);
    mma_gemm<0><<<gq, 128>>>(xbh, xbl, 0, C_, qwh, qwl, 0, C_,
                             C_, 1.0f, nullptr, nullptr, 0, C_, qbh, qbl);
    mma_gemm<0><<<gq, 128>>>(xbh, xbl, 0, C_, kwh, kwl, 0, C_,
                             C_, 1.0f, nullptr, nullptr, 0, C_, kbh, kbl);
    // vT[c][s] = sum_k V^T[c][k]*xn[s][k]: M=C, N=BS
    dim3 gv(BS_ / 128, C_ / 128, 1);
    mma_gemm<0><<<gv, 128>>>(vwh, vwl, 0, C_, xbh, xbl, 0, C_,
                             C_, 1.0f, nullptr, nullptr, 0, BS_, vth, vtl);

    // 5) scores[b][q][k'] = (q.k')/sqrt(C), fp32: M=N=S, K=C, batched
    dim3 gs(S_ / 128, S_ / 128, B_);
    mma_gemm<2><<<gs, 128>>>(qbh, qbl, (size_t)S_ * C_, C_,
                             kbh, kbl, (size_t)S_ * C_, C_,
                             C_, 0.04419417382415922f,
                             sc, nullptr, (size_t)S_ * S_, S_, nullptr, nullptr);

    // 6) batch softmax + split W
    softmax_batch_kernel<<<(S_ * S_) / 256, 256>>>();

    // 7) out[b][s][c] = sum_j W[b][s][j]*vT[c][b*S+j] + xn: M=S, N=C, K=S
    dim3 ga(C_ / 128, S_ / 128, B_);
    mma_gemm<3><<<ga, 128>>>(wth, wtl, (size_t)S_ * S_, S_,
                             vth, vtl, (size_t)S_, BS_,
                             S_, 1.0f,
                             out, xn, (size_t)S_ * C_, C_, nullptr, nullptr);
}